// round 9
// baseline (speedup 1.0000x reference)
#include <cuda_runtime.h>
#include <cuda_bf16.h>

// ChannelPruner: out[b,o,h,w] = sum_c w[o,c] * x[b,c,h,w]
// x: (32, 256, 56, 56) fp32; w: (256,256,1,1) fp32, sparse rows discovered at
// runtime (correct for ANY w).
//
// R9: persistent grid-stride apply kernel (888 = 148x6 resident blocks, each
// ~9 plane-iterations) so x-load bursts pipeline across iterations instead of
// paying a block setup/drain bubble per plane. Next iteration's CSR metadata
// is prefetched in the shadow of the current load burst. CSR built by a ~0.3us
// pre-kernel (proven).

#define N_CH    256
#define BATCH   32
#define HW4     784                   // (56*56)/4 float4 per plane
#define BSTRIDE (N_CH * HW4)
#define NPLANE  (BATCH * N_CH)        // 8192
#define NBLK    (148 * 6)             // 888 persistent blocks, all resident

// Per-row compacted CSR (fully overwritten each launch; graph-replay safe).
__device__ int   g_nnz[N_CH];
__device__ int   g_cols[N_CH * N_CH];
__device__ float g_vals[N_CH * N_CH];

// ---------------------------------------------------------------------------
// Kernel 1: one warp per weight row, compact nonzeros via warp scan. (~0.3us)
// ---------------------------------------------------------------------------
__global__ __launch_bounds__(256) void build_csr(const float* __restrict__ w) {
    const int row  = blockIdx.x * 8 + (threadIdx.x >> 5);
    const int lane = threadIdx.x & 31;
    const float* wr = w + row * N_CH;

    float v[8];
    int cnt = 0;
    const int base = lane * 8;
#pragma unroll
    for (int k = 0; k < 8; k++) {
        v[k] = wr[base + k];
        if (v[k] != 0.0f) cnt++;
    }
    int scan = cnt;                               // inclusive warp scan
#pragma unroll
    for (int d = 1; d < 32; d <<= 1) {
        int t = __shfl_up_sync(0xffffffffu, scan, d);
        if (lane >= d) scan += t;
    }
    const int total = __shfl_sync(0xffffffffu, scan, 31);
    int p = row * N_CH + (scan - cnt);
#pragma unroll
    for (int k = 0; k < 8; k++) {
        if (v[k] != 0.0f) { g_cols[p] = base + k; g_vals[p] = v[k]; p++; }
    }
    if (lane == 31) g_nnz[row] = total;
}

// ---------------------------------------------------------------------------
// Kernel 2: persistent grid-stride over planes; MLP-4 burst per plane with
// next-plane metadata prefetched in the load shadow. No smem, no barriers.
// ---------------------------------------------------------------------------
__global__ __launch_bounds__(256, 6) void apply_csr(const float4* __restrict__ x,
                                                    float4* __restrict__ out) {
    const int  tid  = threadIdx.x;
    const bool tail = tid < (HW4 - 768);          // tid < 16
    const float4 z  = make_float4(0.f, 0.f, 0.f, 0.f);

    int bo = blockIdx.x;

    // metadata for first plane
    int   o   = bo & (N_CH - 1);
    int   nnz = __ldg(&g_nnz[o]);
    int   c0  = __ldg(&g_cols[o * N_CH]);
    float v0  = __ldg(&g_vals[o * N_CH]);

    while (bo < NPLANE) {
        const int   cur_o   = o;
        const int   cur_nnz = nnz;
        const int   cur_c0  = c0;
        const float cur_v0  = v0;
        const int   bo_n    = bo + NBLK;

        const float4* xb = x + (size_t)(bo >> 8) * BSTRIDE;

        float4 a0 = z, a1 = z, a2 = z, a3 = z;

        // issue the long-latency x burst first (if any work)
        float4 r0 = z, r1 = z, r2 = z, r3 = z;
        if (cur_nnz > 0) {
            const float4* xc = xb + (size_t)cur_c0 * HW4 + tid;
            r0 = __ldg(xc);
            r1 = __ldg(xc + 256);
            r2 = __ldg(xc + 512);
            if (tail) r3 = __ldg(xc + 768);
        }

        // prefetch next plane's metadata in the load shadow
        if (bo_n < NPLANE) {
            o   = bo_n & (N_CH - 1);
            nnz = __ldg(&g_nnz[o]);
            c0  = __ldg(&g_cols[o * N_CH]);
            v0  = __ldg(&g_vals[o * N_CH]);
        }

        if (cur_nnz > 0) {
            a0.x += cur_v0 * r0.x; a0.y += cur_v0 * r0.y; a0.z += cur_v0 * r0.z; a0.w += cur_v0 * r0.w;
            a1.x += cur_v0 * r1.x; a1.y += cur_v0 * r1.y; a1.z += cur_v0 * r1.z; a1.w += cur_v0 * r1.w;
            a2.x += cur_v0 * r2.x; a2.y += cur_v0 * r2.y; a2.z += cur_v0 * r2.z; a2.w += cur_v0 * r2.w;
            if (tail) {
                a3.x += cur_v0 * r3.x; a3.y += cur_v0 * r3.y; a3.z += cur_v0 * r3.z; a3.w += cur_v0 * r3.w;
            }
            // general path: remaining nonzeros of this row
#pragma unroll 1
            for (int j = 1; j < cur_nnz; j++) {
                const int   c = __ldg(&g_cols[cur_o * N_CH + j]);
                const float v = __ldg(&g_vals[cur_o * N_CH + j]);
                const float4* xc = xb + (size_t)c * HW4 + tid;
                const float4 s0 = __ldg(xc);
                const float4 s1 = __ldg(xc + 256);
                const float4 s2 = __ldg(xc + 512);
                float4 s3 = z;
                if (tail) s3 = __ldg(xc + 768);
                a0.x += v * s0.x; a0.y += v * s0.y; a0.z += v * s0.z; a0.w += v * s0.w;
                a1.x += v * s1.x; a1.y += v * s1.y; a1.z += v * s1.z; a1.w += v * s1.w;
                a2.x += v * s2.x; a2.y += v * s2.y; a2.z += v * s2.z; a2.w += v * s2.w;
                if (tail) {
                    a3.x += v * s3.x; a3.y += v * s3.y; a3.z += v * s3.z; a3.w += v * s3.w;
                }
            }
        }

        float4* ob = out + (size_t)bo * HW4 + tid;
        __stwt(ob,       a0);
        __stwt(ob + 256, a1);
        __stwt(ob + 512, a2);
        if (tail) __stwt(ob + 768, a3);

        bo = bo_n;
    }
}

extern "C" void kernel_launch(void* const* d_in, const int* in_sizes, int n_in,
                              void* d_out, int out_size) {
    const float4* x = (const float4*)d_in[0];
    const float*  w = (const float*)d_in[1];
    float4* out = (float4*)d_out;

    build_csr<<<32, 256>>>(w);
    apply_csr<<<NBLK, 256>>>(x, out);
}

// round 10
// speedup vs baseline: 1.1171x; 1.1171x over previous
#include <cuda_runtime.h>
#include <cuda_bf16.h>
#include <cstdint>

// ChannelPruner: out[b,o,h,w] = sum_c w[o,c] * x[b,c,h,w]
// x: (32, 256, 56, 56) fp32; w: (256,256,1,1) fp32, sparse rows discovered at
// runtime (correct for ANY w).
//
// R10 = R7 (best shape: fused, 8192 one-plane blocks, 256 thr, MLP-4 LDG,
// occ 8 blocks/SM) with the store path moved off the LSU: accumulate into a
// 12.5KB smem plane buffer (STS, crossbar-cheap), then ONE cp.async.bulk
// (TMA) store of the whole plane per block. Removes ~200K warp STG.128 ops
// (12 cyc LSU issue each) from the load/store pipe.

#define N_CH        256
#define BATCH       32
#define HW4         784                   // (56*56)/4 float4 per plane
#define NPLANE      (BATCH * N_CH)        // 8192 blocks
#define PLANE_BYTES (HW4 * 16)            // 12544 B, 16B-multiple

__device__ __forceinline__ uint32_t smem_u32(const void* p) {
    uint32_t a;
    asm("{ .reg .u64 t; cvta.to.shared.u64 t, %1; cvt.u32.u64 %0, t; }"
        : "=r"(a) : "l"(p));
    return a;
}

__global__ __launch_bounds__(256, 8) void prune_fused(const float4* __restrict__ x,
                                                      const float*  __restrict__ w,
                                                      float4* __restrict__ out) {
    __shared__ alignas(128) float4 s_out[HW4];   // 12544 B staging
    __shared__ int   s_cols[N_CH];
    __shared__ float s_vals[N_CH];
    __shared__ int   s_warp_off[9];

    const int tid  = threadIdx.x;
    const int lane = tid & 31;
    const int wid  = tid >> 5;

    const int bo = blockIdx.x;        // plane index b*256 + o
    const int o  = bo & (N_CH - 1);

    // ---- prologue: deterministic compaction of w row o (proven R2/R7) ----
    const float wv = __ldg(&w[o * N_CH + tid]);
    const unsigned mask = __ballot_sync(0xffffffffu, wv != 0.0f);
    if (lane == 0) s_warp_off[wid + 1] = __popc(mask);
    __syncthreads();
    if (tid == 0) {
        int acc = 0;
        s_warp_off[0] = 0;
#pragma unroll
        for (int i = 0; i < 8; i++) { acc += s_warp_off[i + 1]; s_warp_off[i + 1] = acc; }
    }
    __syncthreads();
    if (wv != 0.0f) {
        const int pos = s_warp_off[wid] + __popc(mask & ((1u << lane) - 1u));
        s_cols[pos] = tid;
        s_vals[pos] = wv;
    }
    __syncthreads();

    const int nnz = s_warp_off[8];

    // ---- body: 4 float4 outputs per thread, MLP-4 LDG bursts ----
    float4 z = make_float4(0.f, 0.f, 0.f, 0.f);
    float4 a0 = z, a1 = z, a2 = z, a3 = z;

    const float4* xb = x + (size_t)(bo >> 8) * (N_CH * HW4);
    const bool tail = tid < (HW4 - 768);          // tid < 16

    for (int j = 0; j < nnz; j++) {
        const int   c = s_cols[j];
        const float v = s_vals[j];
        const float4* xc = xb + (size_t)c * HW4 + tid;
        const float4 r0 = __ldg(xc);
        const float4 r1 = __ldg(xc + 256);
        const float4 r2 = __ldg(xc + 512);
        float4 r3 = z;
        if (tail) r3 = __ldg(xc + 768);

        a0.x += v * r0.x; a0.y += v * r0.y; a0.z += v * r0.z; a0.w += v * r0.w;
        a1.x += v * r1.x; a1.y += v * r1.y; a1.z += v * r1.z; a1.w += v * r1.w;
        a2.x += v * r2.x; a2.y += v * r2.y; a2.z += v * r2.z; a2.w += v * r2.w;
        if (tail) {
            a3.x += v * r3.x; a3.y += v * r3.y; a3.z += v * r3.z; a3.w += v * r3.w;
        }
    }

    // ---- epilogue: stage to smem, then ONE TMA bulk store of the plane ----
    s_out[tid]       = a0;
    s_out[tid + 256] = a1;
    s_out[tid + 512] = a2;
    if (tail) s_out[tid + 768] = a3;
    __syncthreads();

    if (tid == 0) {
        asm volatile("fence.proxy.async.shared::cta;" ::: "memory");
        const uint32_t src = smem_u32(s_out);
        float4* dst = out + (size_t)bo * HW4;
        asm volatile(
            "cp.async.bulk.global.shared::cta.bulk_group [%0], [%1], %2;"
            :: "l"(dst), "r"(src), "r"((uint32_t)PLANE_BYTES) : "memory");
        asm volatile("cp.async.bulk.commit_group;" ::: "memory");
        // wait until the TMA engine has finished READING smem before the
        // block exits (smem may be reallocated to the next block).
        asm volatile("cp.async.bulk.wait_group.read 0;" ::: "memory");
    }
}

extern "C" void kernel_launch(void* const* d_in, const int* in_sizes, int n_in,
                              void* d_out, int out_size) {
    const float4* x = (const float4*)d_in[0];
    const float*  w = (const float*)d_in[1];
    float4* out = (float4*)d_out;

    prune_fused<<<NPLANE, 256>>>(x, w, out);
}